// round 15
// baseline (speedup 1.0000x reference)
#include <cuda_runtime.h>
#include <math.h>

#define DD     2048
#define NS     16
#define NP     8               // mode pairs
#define BB     2
#define LL     4096
#define NCHAN  (BB * DD)
#define CHUNK  (LL / 32)

typedef unsigned long long u64;

__device__ int g_ctr;
__global__ void reset_ctr_kernel() { g_ctr = 0; }

__device__ __forceinline__ u64 pk2(float lo, float hi) {
    u64 r; asm("mov.b64 %0, {%1,%2};" : "=l"(r) : "f"(lo), "f"(hi)); return r;
}
__device__ __forceinline__ void upk2(u64 v, float& lo, float& hi) {
    asm("mov.b64 {%0,%1}, %2;" : "=f"(lo), "=f"(hi) : "l"(v));
}
__device__ __forceinline__ u64 ffma2(u64 a, u64 b, u64 c) {
    u64 d; asm("fma.rn.f32x2 %0, %1, %2, %3;" : "=l"(d) : "l"(a), "l"(b), "l"(c)); return d;
}
__device__ __forceinline__ u64 fmul2(u64 a, u64 b) {
    u64 d; asm("mul.rn.f32x2 %0, %1, %2;" : "=l"(d) : "l"(a), "l"(b)); return d;
}
__device__ __forceinline__ u64 fadd2(u64 a, u64 b) {
    u64 d; asm("add.rn.f32x2 %0, %1, %2;" : "=l"(d) : "l"(a), "l"(b)); return d;
}
__device__ __forceinline__ float sigm(float v) {
    return __fdividef(1.0f, 1.0f + __expf(-v));
}

__global__ __launch_bounds__(128, 4) void cema_kernel(
    const float* __restrict__ x,      // (B, D, L)
    const float* __restrict__ alpha,  // (D, N)
    const float* __restrict__ delta,  // (D, N)
    const float* __restrict__ theta,  // (D)
    const float* __restrict__ gamma,  // (D, N, 2)
    const float* __restrict__ omega,  // (D)
    float* __restrict__ out)          // y (B,D,L) then h (B,D,N,2)
{
    const int lane = threadIdx.x & 31;

    for (;;) {
        // ---- dynamic channel grab ----
        int ch;
        if (lane == 0) ch = atomicAdd(&g_ctr, 1);
        ch = __shfl_sync(0xFFFFFFFFu, ch, 0);
        if (ch >= NCHAN) break;
        const int d = ch & (DD - 1);

        const float base = sigm(theta[d]) * (6.283185307179586f / 16.0f);
        const float om   = omega[d];

        // ---- coefficients. cos/sin of (n+1)*base via rotation recurrence
        //      (one __sincosf total instead of 16).
        //      a1 = 2*Re(q), a2 = -|q|^2, b0 = Re(c), b1 = -Re(c*conj(q)). ----
        u64 A1[NP], A2[NP], B0[NP], B1[NP];
        unsigned qsign = 0u;
        float magmax = 0.0f;
        float cb, sb;
        __sincosf(base, &sb, &cb);
        float cn = cb, sn = sb;            // angle = 1*base (n = 0)
        #pragma unroll
        for (int j = 0; j < NP; j++) {
            float a1v[2], a2v[2], b0v[2], b1v[2];
            #pragma unroll
            for (int h = 0; h < 2; h++) {
                int n = 2 * j + h;
                float p   = sigm(alpha[d * NS + n]);
                float de  = sigm(delta[d * NS + n]);
                float mag = 1.0f - p * de;
                magmax = fmaxf(magmax, mag);
                if (sn < 0.0f) qsign |= (1u << n);
                float qr = mag * cn, qi = mag * sn;
                a1v[h] = 2.0f * qr;
                a2v[h] = -(mag * mag);
                float cr = p * gamma[(d * NS + n) * 2 + 0] * 0.25f;
                float ci = p * gamma[(d * NS + n) * 2 + 1] * 0.25f;
                b0v[h] = cr;
                b1v[h] = -fmaf(cr, qr, ci * qi);
                // rotate to next angle
                float cnx = fmaf(cn, cb, -(sn * sb));
                float snx = fmaf(sn, cb,   cn * sb);
                cn = cnx; sn = snx;
            }
            A1[j] = pk2(a1v[0], a1v[1]);
            A2[j] = pk2(a2v[0], a2v[1]);
            B0[j] = pk2(b0v[0], b0v[1]);
            B1[j] = pk2(b1v[0], b1v[1]);
        }

        // ---- adaptive warm-up length: magmax^K <= e^-9 (~1.2e-4 local,
        //      diluted ~10x globally), multiple of 8, clamped [8, 128]. ----
        int K = (int)ceilf(__fdividef(9.0f, -__logf(magmax)));
        K = min(K, CHUNK);
        K = (K + 7) & ~7;
        K = max(K, 8);
        const int nwu = K >> 3;

        const size_t chbase = (size_t)ch * LL;
        const float4* __restrict__ xbase =
            (const float4*)(x + chbase + (size_t)lane * CHUNK);

        // ---- warm-up: recurrence over the last K steps of the previous
        //      lane's chunk from zero state (lane 0: re-zeroed after). ----
        u64 W[NP], Wp[NP];
        #pragma unroll
        for (int j = 0; j < NP; j++) { W[j] = 0ull; Wp[j] = 0ull; }

        {
            const float4* wb4 = (lane == 0) ? xbase
                : (const float4*)(x + chbase + (size_t)lane * CHUNK - K);
            const float4* xp = wb4;
            float4 c0 = xp[0], c1 = xp[1];
            #pragma unroll 1
            for (int i = 0; i < nwu; i++) {
                const float4* np = (i + 1 < nwu) ? (xp + 2) : wb4;
                float4 n0 = np[0], n1 = np[1];
                float xs[8] = { c0.x, c0.y, c0.z, c0.w, c1.x, c1.y, c1.z, c1.w };
                #pragma unroll
                for (int k = 0; k < 8; k++) {
                    u64 X = pk2(xs[k], xs[k]);
                    #pragma unroll
                    for (int j = 0; j < NP; j++) {
                        u64 wn = ffma2(A1[j], W[j], ffma2(A2[j], Wp[j], X));
                        Wp[j] = W[j]; W[j] = wn;
                    }
                }
                c0 = n0; c1 = n1; xp = np;
            }
            if (lane == 0) {
                #pragma unroll
                for (int j = 0; j < NP; j++) { W[j] = 0ull; Wp[j] = 0ull; }
            }
        }

        // ---- main pass: 128 steps over own chunk, emit y.
        //      acc init via fmul2 (no zero movs); x*om folded scalarly. ----
        float4* __restrict__ ybase = (float4*)(out + chbase + (size_t)lane * CHUNK);
        {
            const float4* xp = xbase;
            float4* yp = ybase;
            float4 c0 = xp[0], c1 = xp[1];
            #pragma unroll 1
            for (int i = 0; i < 16; i++) {
                const float4* np = (i < 15) ? (xp + 2) : xbase;
                float4 n0 = np[0], n1 = np[1];
                float xs[8] = { c0.x, c0.y, c0.z, c0.w, c1.x, c1.y, c1.z, c1.w };
                float ys[8];
                #pragma unroll
                for (int k = 0; k < 8; k++) {
                    float xk = xs[k];
                    u64 X = pk2(xk, xk);
                    u64 acc0, acc1;
                    #pragma unroll
                    for (int j = 0; j < NP; j++) {
                        u64 wn = ffma2(A1[j], W[j], ffma2(A2[j], Wp[j], X));
                        if (j == 0) {
                            acc0 = fmul2(B0[0], wn);
                            acc0 = ffma2(B1[0], W[0], acc0);
                        } else if (j == 1) {
                            acc1 = fmul2(B0[1], wn);
                            acc1 = ffma2(B1[1], W[1], acc1);
                        } else if (j & 1) {
                            acc1 = ffma2(B0[j], wn,   acc1);
                            acc1 = ffma2(B1[j], W[j], acc1);
                        } else {
                            acc0 = ffma2(B0[j], wn,   acc0);
                            acc0 = ffma2(B1[j], W[j], acc0);
                        }
                        Wp[j] = W[j]; W[j] = wn;
                    }
                    u64 s = fadd2(acc0, acc1);
                    float lo, hi;
                    upk2(s, lo, hi);
                    ys[k] = fmaf(xk, om, lo + hi);
                }
                yp[0] = make_float4(ys[0], ys[1], ys[2], ys[3]);
                yp[1] = make_float4(ys[4], ys[5], ys[6], ys[7]);
                c0 = n0; c1 = n1; xp = np; yp += 2;
            }
        }

        // ---- h from lane 31's final states: qr = a1/2,
        //      |qi| = sqrt(-a2 - qr^2) signed by qsign; h = p * S[L-1],
        //      S[L-1] = w[L-1] - conj(q) * w[L-2]. ----
        if (lane == 31) {
            float* hptr = out + (size_t)BB * DD * LL + (size_t)ch * NS * 2;
            #pragma unroll
            for (int j = 0; j < NP; j++) {
                float a1v[2], a2v[2], wv[2], wpv[2];
                upk2(A1[j], a1v[0], a1v[1]);
                upk2(A2[j], a2v[0], a2v[1]);
                upk2(W[j],  wv[0],  wv[1]);
                upk2(Wp[j], wpv[0], wpv[1]);
                #pragma unroll
                for (int h = 0; h < 2; h++) {
                    int n = 2 * j + h;
                    float qr = 0.5f * a1v[h];
                    float qi = __fsqrt_rn(fmaxf(fmaf(-qr, qr, -a2v[h]), 0.0f));
                    if (qsign & (1u << n)) qi = -qi;
                    float p  = sigm(alpha[d * NS + n]);
                    hptr[2 * n + 0] = p * fmaf(-qr, wpv[h], wv[h]);
                    hptr[2 * n + 1] = p * (qi * wpv[h]);
                }
            }
        }
    }
}

extern "C" void kernel_launch(void* const* d_in, const int* in_sizes, int n_in,
                              void* d_out, int out_size)
{
    const float* x     = (const float*)d_in[0];
    const float* alpha = (const float*)d_in[1];
    const float* delta = (const float*)d_in[2];
    const float* theta = (const float*)d_in[3];
    const float* gamma = (const float*)d_in[4];
    const float* omega = (const float*)d_in[5];
    float* out = (float*)d_out;

    reset_ctr_kernel<<<1, 1>>>();
    // Persistent grid: 4 CTAs/SM x 152 SMs; warps pull channels dynamically.
    cema_kernel<<<608, 128>>>(x, alpha, delta, theta, gamma, omega, out);
}